// round 7
// baseline (speedup 1.0000x reference)
#include <cuda_runtime.h>
#include <cstdint>

// Unfold (im2col): x[32,64,64,64] f32, 3x3/s1 -> out[32,576,3844] f32
// out[(bc*9+3ki+kj)][l+e] = ch[ki*64 + kj + (l+e) + 2*floor((l+e)/62)]
//
// Block = (channel, half-of-L). Stage just the 34 needed input rows (8.7KB,
// pitch-33 padded -> conflict-free). Per float4 m and ki, the 12 elements
// (kj=0..2, e=0..3) come from the 8-word window C..C+7; row-crossing (j0==60)
// folds in via 6 SELs. 8 LDS + 6 SEL + 3 STG.128 per (m,ki).
// Half-split + launch_bounds(256,6): 4096 blocks, ~75% occ, small wave tail.

#define HW     64
#define CH     4096
#define WO     62
#define L      3844
#define NV4    961            // float4 per output row
#define BASEW  1920           // word offset of half1 stage (row 30; 1920%32==0)
#define NWST   2176           // words staged per block (34 rows)
#define SMW    2248           // PADI(2177)=2245 max touched (slack overread)

__device__ __forceinline__ int PADI(int w) { return w + (w >> 5); }

__global__ __launch_bounds__(256, 6)
void unfold_kernel(const float* __restrict__ x, float* __restrict__ out)
{
    __shared__ float sm[SMW];

    const int bc   = blockIdx.x;              // 0..2047  (b*64 + c)
    const int half = blockIdx.y;              // 0..1
    const int base = half ? BASEW : 0;        // word offset of staged region
    const int tid  = threadIdx.x;

    // ---- stage 2176 words (34 rows) into padded smem ----
    {
        const float4* __restrict__ s4 =
            reinterpret_cast<const float4*>(x + (size_t)bc * CH + base);
#pragma unroll
        for (int v = tid; v < NWST / 4; v += 256) {   // 544 = 2*256 + 32
            float4 d = s4[v];
            int w = 4 * v;
            sm[PADI(w + 0)] = d.x;
            sm[PADI(w + 1)] = d.y;
            sm[PADI(w + 2)] = d.z;
            sm[PADI(w + 3)] = d.w;
        }
    }
    __syncthreads();

    float4* __restrict__ dst4 =
        reinterpret_cast<float4*>(out + (size_t)bc * 9 * L);

    const int mstart = half ? 480 : 0;
    const int mend   = half ? NV4 : 480;

#pragma unroll
    for (int it = 0; it < 2; ++it) {
        const int m = mstart + it * 256 + tid;
        if (m < mend) {
            const int l   = 4 * m;
            const int i0  = l / WO;           // const divisor -> mulhi
            const int j0  = l - WO * i0;
            const int b0  = l + 2 * i0 - base;
            const bool cr = (j0 == 60);       // only e=2,3 cross, +2 words

#pragma unroll
            for (int ki = 0; ki < 3; ++ki) {
                const int C = ki * HW + b0;

                const float s0 = sm[PADI(C + 0)];
                const float s1 = sm[PADI(C + 1)];
                const float s2 = sm[PADI(C + 2)];
                const float s3 = sm[PADI(C + 3)];
                const float s4 = sm[PADI(C + 4)];
                const float s5 = sm[PADI(C + 5)];
                const float s6 = sm[PADI(C + 6)];
                const float s7 = sm[PADI(C + 7)];

                float4 v;
                // kj = 0
                v.x = s0; v.y = s1;
                v.z = cr ? s4 : s2; v.w = cr ? s5 : s3;
                dst4[(3 * ki + 0) * NV4 + m] = v;
                // kj = 1
                v.x = s1; v.y = s2;
                v.z = cr ? s5 : s3; v.w = cr ? s6 : s4;
                dst4[(3 * ki + 1) * NV4 + m] = v;
                // kj = 2
                v.x = s2; v.y = s3;
                v.z = cr ? s6 : s4; v.w = cr ? s7 : s5;
                dst4[(3 * ki + 2) * NV4 + m] = v;
            }
        }
    }
}

extern "C" void kernel_launch(void* const* d_in, const int* in_sizes, int n_in,
                              void* d_out, int out_size)
{
    const float* x = (const float*)d_in[0];
    float* out = (float*)d_out;

    dim3 grid(2048, 2, 1);                    // (channel, half-of-L)
    unfold_kernel<<<grid, 256>>>(x, out);
}